// round 2
// baseline (speedup 1.0000x reference)
#include <cuda_runtime.h>
#include <cstdint>

#define BB   8
#define NN   4096
#define DD   1024
#define NQ   64
#define KTOP 1024
#define NEG_INF (__int_as_float(0xff800000))

// ---------------- scratch (device globals; no allocation allowed) ----------------
__device__ float g_QWT[DD * NQ];                    // QW transposed: [d][q]
__device__ float g_db [BB * NN];                    // density bias per token
__device__ float g_S  [(size_t)BB * NN * NQ];       // scores, layout [b][n][q]  (8 MB)
__device__ float g_pm [BB * 32 * NQ];               // partial max  [b][chunk][q]
__device__ float g_pz [BB * 32 * NQ];               // partial sumexp
__device__ float g_lq [BB * NQ];                    // m + log z per (b,q)
__device__ float g_r  [BB * NN];                    // max_q (S - lq)
__device__ int   g_idx[BB * KTOP];                  // selected indices (ascending)

// packed fp32x2 FMA (Blackwell): d = a*b + d on both 32-bit halves
__device__ __forceinline__ void ffma2(unsigned long long& d,
                                      unsigned long long a,
                                      unsigned long long b) {
    asm("fma.rn.f32x2 %0, %1, %2, %0;" : "+l"(d) : "l"(a), "l"(b));
}
__device__ __forceinline__ float f2lo(unsigned long long v) {
    return __uint_as_float((unsigned)v);
}
__device__ __forceinline__ float f2hi(unsigned long long v) {
    return __uint_as_float((unsigned)(v >> 32));
}

// ---------------- K1: QWT[d][q] = sum_h qe[q][h] * kw[d][h] ----------------
// grid 128 blocks (8 d-rows each), 256 threads
__global__ void k1_qw(const float* __restrict__ qe, const float* __restrict__ kw) {
    __shared__ float qs[64][132];   // padded: bank = (4q + k) % 32, conflict-free
    __shared__ float ks[8][132];
    const int t  = threadIdx.x;
    const int j0 = blockIdx.x * 8;
    const int q  = t >> 2;          // 0..63
    const int jl = (t & 3) * 2;     // 0,2,4,6

    float acc0 = 0.f, acc1 = 0.f;
    for (int c = 0; c < 8; ++c) {
        const int k0 = c * 128;
        __syncthreads();
        // stage qe[0:64][k0:k0+128]
        #pragma unroll
        for (int p = 0; p < 8; ++p) {
            int f = t + 256 * p;
            int qq = f >> 5, kk = (f & 31) * 4;
            *(float4*)&qs[qq][kk] = *(const float4*)&qe[qq * 1024 + k0 + kk];
        }
        // stage kw[j0:j0+8][k0:k0+128]
        {
            int dr = t >> 5, kk = (t & 31) * 4;
            *(float4*)&ks[dr][kk] = *(const float4*)&kw[(j0 + dr) * 1024 + k0 + kk];
        }
        __syncthreads();
        #pragma unroll 8
        for (int kk = 0; kk < 128; kk += 4) {
            float4 a  = *(const float4*)&qs[q][kk];
            float4 b0 = *(const float4*)&ks[jl][kk];
            float4 b1 = *(const float4*)&ks[jl + 1][kk];
            acc0 += a.x * b0.x + a.y * b0.y + a.z * b0.z + a.w * b0.w;
            acc1 += a.x * b1.x + a.y * b1.y + a.z * b1.z + a.w * b1.w;
        }
    }
    g_QWT[(j0 + jl)     * 64 + q] = acc0;
    g_QWT[(j0 + jl + 1) * 64 + q] = acc1;
}

// ---------------- K2: density bias per token ----------------
// db = sum_j relu(t*w1[j] + b1[j]) * w2[j] + b2 ; warp per token, 8 tokens/block
__global__ void k2_density(const float* __restrict__ dens,
                           const float* __restrict__ w1, const float* __restrict__ b1,
                           const float* __restrict__ w2, const float* __restrict__ b2) {
    __shared__ float w1s[2048], b1s[2048], w2s[2048];
    const int t = threadIdx.x;
    for (int i = t; i < 512; i += 256) {
        *(float4*)&w1s[i * 4] = *(const float4*)&w1[i * 4];
        *(float4*)&b1s[i * 4] = *(const float4*)&b1[i * 4];
        *(float4*)&w2s[i * 4] = *(const float4*)&w2[i * 4];
    }
    __syncthreads();
    const int lane = t & 31, w = t >> 5;
    const int tok = blockIdx.x * 8 + w;
    const float td = dens[tok];
    float s = 0.f;
    #pragma unroll 8
    for (int j = lane; j < 2048; j += 32) {
        float h = fmaf(td, w1s[j], b1s[j]);
        s += fmaxf(h, 0.f) * w2s[j];
    }
    #pragma unroll
    for (int o = 16; o > 0; o >>= 1) s += __shfl_xor_sync(0xffffffffu, s, o);
    if (lane == 0) g_db[tok] = s + b2[0];
}

// ---------------- K3: main GEMM  S[b][n][q] = X[b,n,:]·QW[q,:]/32 + db ----------------
// grid (32, 8), 256 threads. Tile 128 rows x 64 cols, KC=16, FFMA2 inner loop.
#define KC3 16
__global__ void __launch_bounds__(256, 2)
k3_scores(const float* __restrict__ X) {
    __shared__ float2 Xs[KC3][130];   // duplicated halves; row = 1040B (16B aligned)
    __shared__ float  Bs[KC3][64];
    const int b  = blockIdx.y;
    const int n0 = blockIdx.x * 128;
    const int t  = threadIdx.x;
    const int tx = t & 7, ty = t >> 3;             // tx: col-group, ty: row-group
    const float* Xb = X + ((size_t)b * NN + n0) * (size_t)DD;

    unsigned long long acc[4][4];
    #pragma unroll
    for (int i = 0; i < 4; ++i)
        #pragma unroll
        for (int j = 0; j < 4; ++j) acc[i][j] = 0ull;

    // prefetch chunk 0 into regs
    float4 xg[2], bg;
    {
        const int f0 = t, f1 = t + 256;
        xg[0] = *(const float4*)&Xb[(f0 >> 2) * DD + (f0 & 3) * 4];
        xg[1] = *(const float4*)&Xb[(f1 >> 2) * DD + (f1 & 3) * 4];
        bg    = *(const float4*)&g_QWT[(t >> 4) * 64 + (t & 15) * 4];
    }

    for (int c = 0; c < DD / KC3; ++c) {
        __syncthreads();
        // store staged regs -> shared (A duplicated into both f32x2 halves)
        #pragma unroll
        for (int p = 0; p < 2; ++p) {
            int f = t + 256 * p;
            int r = f >> 2, kkg = (f & 3) * 4;
            Xs[kkg + 0][r] = make_float2(xg[p].x, xg[p].x);
            Xs[kkg + 1][r] = make_float2(xg[p].y, xg[p].y);
            Xs[kkg + 2][r] = make_float2(xg[p].z, xg[p].z);
            Xs[kkg + 3][r] = make_float2(xg[p].w, xg[p].w);
        }
        *(float4*)&Bs[t >> 4][(t & 15) * 4] = bg;
        __syncthreads();
        if (c + 1 < DD / KC3) {
            const int k0 = (c + 1) * KC3;
            const int f0 = t, f1 = t + 256;
            xg[0] = *(const float4*)&Xb[(f0 >> 2) * DD + k0 + (f0 & 3) * 4];
            xg[1] = *(const float4*)&Xb[(f1 >> 2) * DD + k0 + (f1 & 3) * 4];
            bg    = *(const float4*)&g_QWT[(k0 + (t >> 4)) * 64 + (t & 15) * 4];
        }
        #pragma unroll
        for (int k = 0; k < KC3; ++k) {
            ulonglong2 a0 = *(const ulonglong2*)&Xs[k][ty * 4];
            ulonglong2 a1 = *(const ulonglong2*)&Xs[k][ty * 4 + 2];
            ulonglong2 b0 = *(const ulonglong2*)&Bs[k][tx * 8];
            ulonglong2 b1 = *(const ulonglong2*)&Bs[k][tx * 8 + 4];
            ffma2(acc[0][0], a0.x, b0.x); ffma2(acc[0][1], a0.x, b0.y);
            ffma2(acc[0][2], a0.x, b1.x); ffma2(acc[0][3], a0.x, b1.y);
            ffma2(acc[1][0], a0.y, b0.x); ffma2(acc[1][1], a0.y, b0.y);
            ffma2(acc[1][2], a0.y, b1.x); ffma2(acc[1][3], a0.y, b1.y);
            ffma2(acc[2][0], a1.x, b0.x); ffma2(acc[2][1], a1.x, b0.y);
            ffma2(acc[2][2], a1.x, b1.x); ffma2(acc[2][3], a1.x, b1.y);
            ffma2(acc[3][0], a1.y, b0.x); ffma2(acc[3][1], a1.y, b0.y);
            ffma2(acc[3][2], a1.y, b1.x); ffma2(acc[3][3], a1.y, b1.y);
        }
    }

    const float inv = 0.03125f;   // 1/sqrt(1024)
    #pragma unroll
    for (int i = 0; i < 4; ++i) {
        const int n = n0 + ty * 4 + i;
        const float dbv = g_db[(b << 12) + n];
        float4 o0, o1;
        o0.x = fmaf(f2lo(acc[i][0]), inv, dbv); o0.y = fmaf(f2hi(acc[i][0]), inv, dbv);
        o0.z = fmaf(f2lo(acc[i][1]), inv, dbv); o0.w = fmaf(f2hi(acc[i][1]), inv, dbv);
        o1.x = fmaf(f2lo(acc[i][2]), inv, dbv); o1.y = fmaf(f2hi(acc[i][2]), inv, dbv);
        o1.z = fmaf(f2lo(acc[i][3]), inv, dbv); o1.w = fmaf(f2hi(acc[i][3]), inv, dbv);
        float* sp = &g_S[((size_t)(b << 12) + n) * NQ + tx * 8];
        *(float4*)sp       = o0;
        *(float4*)(sp + 4) = o1;
    }
}

// ---------------- K4a: per-(b, n-chunk) partial rowmax + sumexp over n ----------------
__global__ void k4a_partials() {
    __shared__ float sm[8][64], sz[8][64];
    const int b = blockIdx.y, s = blockIdx.x;
    const int t = threadIdx.x, w = t >> 5, lane = t & 31;
    const int q0 = lane * 2;
    float m0 = NEG_INF, m1 = NEG_INF, z0 = 0.f, z1 = 0.f;
    const int nbase = s * 128 + w * 16;
    for (int rr = 0; rr < 16; ++rr) {
        const int n = nbase + rr;
        float2 v = *(const float2*)&g_S[((size_t)(b << 12) + n) * NQ + q0];
        if (v.x > m0) { z0 = z0 * expf(m0 - v.x) + 1.f; m0 = v.x; } else z0 += expf(v.x - m0);
        if (v.y > m1) { z1 = z1 * expf(m1 - v.y) + 1.f; m1 = v.y; } else z1 += expf(v.y - m1);
    }
    sm[w][q0] = m0; sz[w][q0] = z0;
    sm[w][q0 + 1] = m1; sz[w][q0 + 1] = z1;
    __syncthreads();
    if (t < 64) {
        float m = NEG_INF;
        for (int w2 = 0; w2 < 8; ++w2) m = fmaxf(m, sm[w2][t]);
        float z = 0.f;
        for (int w2 = 0; w2 < 8; ++w2) z += sz[w2][t] * expf(sm[w2][t] - m);
        g_pm[(b * 32 + s) * 64 + t] = m;
        g_pz[(b * 32 + s) * 64 + t] = z;
    }
}

// ---------------- K4b: combine partials -> lq = m + log z ----------------
__global__ void k4b_combine() {
    const int t = threadIdx.x;          // 512 = 8*64
    const int b = t >> 6, q = t & 63;
    float m = NEG_INF;
    for (int c = 0; c < 32; ++c) m = fmaxf(m, g_pm[(b * 32 + c) * 64 + q]);
    float z = 0.f;
    for (int c = 0; c < 32; ++c) z += g_pz[(b * 32 + c) * 64 + q] * expf(g_pm[(b * 32 + c) * 64 + q] - m);
    g_lq[b * 64 + q] = m + logf(z);
}

// ---------------- K5: r[b][n] = max_q (S - lq)  (monotone proxy for importance) ------
__global__ void k5_importance() {
    __shared__ float lqs[64];
    const int t = threadIdx.x;
    const int b = blockIdx.x >> 4;
    if (t < 64) lqs[t] = g_lq[b * 64 + t];
    __syncthreads();
    const int tok = blockIdx.x * 256 + t;
    const float4* row = (const float4*)&g_S[(size_t)tok * NQ];
    float m = NEG_INF;
    #pragma unroll
    for (int i = 0; i < 16; ++i) {
        float4 v = row[i];
        m = fmaxf(m, v.x - lqs[i * 4 + 0]);
        m = fmaxf(m, v.y - lqs[i * 4 + 1]);
        m = fmaxf(m, v.z - lqs[i * 4 + 2]);
        m = fmaxf(m, v.w - lqs[i * 4 + 3]);
    }
    g_r[tok] = m;
}

// ---------------- K6: radix top-k select per batch (exact, stable ties) ----------------
__device__ __forceinline__ unsigned ordkey(float f) {
    unsigned u = __float_as_uint(f);
    return (u & 0x80000000u) ? ~u : (u | 0x80000000u);
}
__global__ void k6_select() {
    __shared__ unsigned skey[4096];
    __shared__ unsigned hist[256];
    __shared__ unsigned scanv[256];
    __shared__ unsigned sh_selbin, sh_cum;
    const int t = threadIdx.x;          // 256 threads, 16 keys each (contiguous)
    const int b = blockIdx.x;

    #pragma unroll
    for (int i = 0; i < 4; ++i) {
        float4 v = *(const float4*)&g_r[(b << 12) + t * 16 + i * 4];
        skey[t * 16 + i * 4 + 0] = ordkey(v.x);
        skey[t * 16 + i * 4 + 1] = ordkey(v.y);
        skey[t * 16 + i * 4 + 2] = ordkey(v.z);
        skey[t * 16 + i * 4 + 3] = ordkey(v.w);
    }
    __syncthreads();

    unsigned prefix = 0, prefmask = 0, want = KTOP;
    for (int shift = 24; shift >= 0; shift -= 8) {
        hist[t] = 0;
        __syncthreads();
        for (int e = 0; e < 16; ++e) {
            unsigned k = skey[t * 16 + e];
            if ((k & prefmask) == prefix) atomicAdd(&hist[(k >> shift) & 255u], 1u);
        }
        __syncthreads();
        if (t == 0) {
            unsigned cum = 0; int bin = 255;
            for (; bin >= 0; --bin) {
                unsigned c = hist[bin];
                if (cum + c >= want) break;
                cum += c;
            }
            sh_selbin = (unsigned)bin; sh_cum = cum;
        }
        __syncthreads();
        prefix  |= sh_selbin << shift;
        prefmask |= 0xFFu << shift;
        want    -= sh_cum;
        __syncthreads();
    }
    const unsigned T = prefix;          // exact key of boundary value
    const unsigned budget = want;       // how many == T to take (lowest indices)

    // counts per thread: gt (key > T), eq (key == T)
    unsigned cgt = 0, ceq = 0;
    for (int e = 0; e < 16; ++e) {
        unsigned k = skey[t * 16 + e];
        cgt += (k > T); ceq += (k == T);
    }
    scanv[t] = (cgt << 16) | ceq;
    __syncthreads();
    if (t == 0) {
        unsigned run = 0;
        for (int i = 0; i < 256; ++i) { unsigned v = scanv[i]; scanv[i] = run; run += v; }
    }
    __syncthreads();
    unsigned gtb = scanv[t] >> 16, eqb = scanv[t] & 0xFFFFu;
    for (int e = 0; e < 16; ++e) {
        const int n = t * 16 + e;
        unsigned k = skey[n];
        if (k > T) {
            g_idx[b * KTOP + gtb + min(eqb, budget)] = n;
            gtb++;
        } else if (k == T) {
            if (eqb < budget) g_idx[b * KTOP + gtb + eqb] = n;
            eqb++;
        }
    }
}

// ---------------- K7: gather selected rows ----------------
__global__ void k7_gather(const float* __restrict__ X, float* __restrict__ out) {
    const int row = blockIdx.x;               // 0..8191 = b*1024 + i
    const int b = row >> 10;
    const int src = g_idx[row];
    const float4* s = (const float4*)&X[((size_t)(b << 12) + src) * (size_t)DD];
    float4* d = (float4*)&out[(size_t)row * DD];
    d[threadIdx.x] = s[threadIdx.x];
}

// ---------------- launch ----------------
extern "C" void kernel_launch(void* const* d_in, const int* in_sizes, int n_in,
                              void* d_out, int out_size) {
    const float* X    = (const float*)d_in[0];   // [8,4096,1024]
    const float* dens = (const float*)d_in[1];   // [8,4096]
    const float* qe   = (const float*)d_in[2];   // [64,1024]
    const float* kw   = (const float*)d_in[3];   // [1024,1024]
    // d_in[4] = key_b : per-query constant after Q·b -> softmax-invariant, dropped
    const float* w1   = (const float*)d_in[5];   // [1,2048]
    const float* b1   = (const float*)d_in[6];   // [2048]
    const float* w2   = (const float*)d_in[7];   // [2048,1]
    const float* b2   = (const float*)d_in[8];   // [1]
    float* out = (float*)d_out;

    k1_qw      <<<128, 256>>>(qe, kw);
    k2_density <<<4096, 256>>>(dens, w1, b1, w2, b2);
    k3_scores  <<<dim3(32, 8), 256>>>(X);
    k4a_partials<<<dim3(32, 8), 256>>>();
    k4b_combine<<<1, 512>>>();
    k5_importance<<<128, 256>>>();
    k6_select  <<<8, 256>>>();
    k7_gather  <<<8192, 256>>>(X, out);
}

// round 4
// speedup vs baseline: 1.1489x; 1.1489x over previous
#include <cuda_runtime.h>
#include <cstdint>

#define BB   8
#define NN   4096
#define DD   1024
#define NQ   64
#define KTOP 1024
#define NEG_INF (__int_as_float(0xff800000))

// ---------------- scratch (device globals; no allocation allowed) ----------------
__device__ float g_QWT[DD * NQ];                    // QW transposed: [d][q]
__device__ float g_db [BB * NN];                    // density bias per token
__device__ float g_S  [(size_t)BB * NN * NQ];       // scores, layout [b][n][q]  (8 MB)
__device__ float g_pm [BB * 32 * NQ];               // partial max  [b][chunk][q]
__device__ float g_pz [BB * 32 * NQ];               // partial sumexp
__device__ float g_lq [BB * NQ];                    // m + log z per (b,q)
__device__ float g_r  [BB * NN];                    // max_q (S - lq)
__device__ int   g_idx[BB * KTOP];                  // selected indices (ascending)

// packed fp32x2 FMA (Blackwell): d = a*b + d on both 32-bit halves
__device__ __forceinline__ void ffma2(unsigned long long& d,
                                      unsigned long long a,
                                      unsigned long long b) {
    asm("fma.rn.f32x2 %0, %1, %2, %0;" : "+l"(d) : "l"(a), "l"(b));
}
__device__ __forceinline__ float f2lo(unsigned long long v) {
    return __uint_as_float((unsigned)v);
}
__device__ __forceinline__ float f2hi(unsigned long long v) {
    return __uint_as_float((unsigned)(v >> 32));
}

// ---------------- K1: QWT[d][q] = sum_h qe[q][h] * kw[d][h] ----------------
__global__ void k1_qw(const float* __restrict__ qe, const float* __restrict__ kw) {
    __shared__ float qs[64][132];
    __shared__ float ks[8][132];
    const int t  = threadIdx.x;
    const int j0 = blockIdx.x * 8;
    const int q  = t >> 2;
    const int jl = (t & 3) * 2;

    float acc0 = 0.f, acc1 = 0.f;
    for (int c = 0; c < 8; ++c) {
        const int k0 = c * 128;
        __syncthreads();
        #pragma unroll
        for (int p = 0; p < 8; ++p) {
            int f = t + 256 * p;
            int qq = f >> 5, kk = (f & 31) * 4;
            *(float4*)&qs[qq][kk] = *(const float4*)&qe[qq * 1024 + k0 + kk];
        }
        {
            int dr = t >> 5, kk = (t & 31) * 4;
            *(float4*)&ks[dr][kk] = *(const float4*)&kw[(j0 + dr) * 1024 + k0 + kk];
        }
        __syncthreads();
        #pragma unroll 8
        for (int kk = 0; kk < 128; kk += 4) {
            float4 a  = *(const float4*)&qs[q][kk];
            float4 b0 = *(const float4*)&ks[jl][kk];
            float4 b1 = *(const float4*)&ks[jl + 1][kk];
            acc0 += a.x * b0.x + a.y * b0.y + a.z * b0.z + a.w * b0.w;
            acc1 += a.x * b1.x + a.y * b1.y + a.z * b1.z + a.w * b1.w;
        }
    }
    g_QWT[(j0 + jl)     * 64 + q] = acc0;
    g_QWT[(j0 + jl + 1) * 64 + q] = acc1;
}

// ---------------- K2: density bias; 128 blocks, one token per thread ----------------
__global__ void k2_density(const float* __restrict__ dens,
                           const float* __restrict__ w1, const float* __restrict__ b1,
                           const float* __restrict__ w2, const float* __restrict__ b2) {
    __shared__ float4 w1s[512], b1s[512], w2s[512];
    const int t = threadIdx.x;
    for (int i = t; i < 512; i += 256) {
        w1s[i] = ((const float4*)w1)[i];
        b1s[i] = ((const float4*)b1)[i];
        w2s[i] = ((const float4*)w2)[i];
    }
    __syncthreads();
    const int tok = blockIdx.x * 256 + t;
    const float td = dens[tok];
    float s0 = 0.f, s1 = 0.f, s2 = 0.f, s3 = 0.f;
    #pragma unroll 4
    for (int j = 0; j < 512; ++j) {
        float4 a = w1s[j], bb = b1s[j], c = w2s[j];
        float h;
        h = fmaf(td, a.x, bb.x); s0 += fmaxf(h, 0.f) * c.x;
        h = fmaf(td, a.y, bb.y); s1 += fmaxf(h, 0.f) * c.y;
        h = fmaf(td, a.z, bb.z); s2 += fmaxf(h, 0.f) * c.z;
        h = fmaf(td, a.w, bb.w); s3 += fmaxf(h, 0.f) * c.w;
    }
    g_db[tok] = ((s0 + s1) + (s2 + s3)) + b2[0];
}

// ---------------- K3: GEMM + fused softmax partials ----------------
// grid (32, 8), 256 threads. Tile 128n x 64q, KC=16, FFMA2, double-buffered smem.
#define KC3 16
__global__ void __launch_bounds__(256, 2)
k3_scores(const float* __restrict__ X) {
    __shared__ float2 Xs[2][KC3][130];
    __shared__ float  Bs[2][KC3][64];
    const int b  = blockIdx.y;
    const int n0 = blockIdx.x * 128;
    const int t  = threadIdx.x;
    const int tx = t & 7, ty = t >> 3;
    const float* Xb = X + ((size_t)b * NN + n0) * (size_t)DD;

    unsigned long long acc[4][4];
    #pragma unroll
    for (int i = 0; i < 4; ++i)
        #pragma unroll
        for (int j = 0; j < 4; ++j) acc[i][j] = 0ull;

    float4 xg[2], bg;
    const int f0 = t, f1 = t + 256;
    const int r0 = f0 >> 2, kk0 = (f0 & 3) * 4;
    const int r1 = f1 >> 2, kk1 = (f1 & 3) * 4;

    // prefetch + stage chunk 0 into buffer 0
    xg[0] = *(const float4*)&Xb[r0 * DD + kk0];
    xg[1] = *(const float4*)&Xb[r1 * DD + kk1];
    bg    = *(const float4*)&g_QWT[(t >> 4) * 64 + (t & 15) * 4];
    {
        Xs[0][kk0 + 0][r0] = make_float2(xg[0].x, xg[0].x);
        Xs[0][kk0 + 1][r0] = make_float2(xg[0].y, xg[0].y);
        Xs[0][kk0 + 2][r0] = make_float2(xg[0].z, xg[0].z);
        Xs[0][kk0 + 3][r0] = make_float2(xg[0].w, xg[0].w);
        Xs[0][kk1 + 0][r1] = make_float2(xg[1].x, xg[1].x);
        Xs[0][kk1 + 1][r1] = make_float2(xg[1].y, xg[1].y);
        Xs[0][kk1 + 2][r1] = make_float2(xg[1].z, xg[1].z);
        Xs[0][kk1 + 3][r1] = make_float2(xg[1].w, xg[1].w);
        *(float4*)&Bs[0][t >> 4][(t & 15) * 4] = bg;
    }
    __syncthreads();

    for (int c = 0; c < DD / KC3; ++c) {
        const int cur = c & 1, nxt = cur ^ 1;
        if (c + 1 < DD / KC3) {
            const int k0 = (c + 1) * KC3;
            xg[0] = *(const float4*)&Xb[r0 * DD + k0 + kk0];
            xg[1] = *(const float4*)&Xb[r1 * DD + k0 + kk1];
            bg    = *(const float4*)&g_QWT[(k0 + (t >> 4)) * 64 + (t & 15) * 4];
        }
        #pragma unroll
        for (int k = 0; k < KC3; ++k) {
            ulonglong2 a0 = *(const ulonglong2*)&Xs[cur][k][ty * 4];
            ulonglong2 a1 = *(const ulonglong2*)&Xs[cur][k][ty * 4 + 2];
            ulonglong2 b0 = *(const ulonglong2*)&Bs[cur][k][tx * 8];
            ulonglong2 b1 = *(const ulonglong2*)&Bs[cur][k][tx * 8 + 4];
            ffma2(acc[0][0], a0.x, b0.x); ffma2(acc[0][1], a0.x, b0.y);
            ffma2(acc[0][2], a0.x, b1.x); ffma2(acc[0][3], a0.x, b1.y);
            ffma2(acc[1][0], a0.y, b0.x); ffma2(acc[1][1], a0.y, b0.y);
            ffma2(acc[1][2], a0.y, b1.x); ffma2(acc[1][3], a0.y, b1.y);
            ffma2(acc[2][0], a1.x, b0.x); ffma2(acc[2][1], a1.x, b0.y);
            ffma2(acc[2][2], a1.x, b1.x); ffma2(acc[2][3], a1.x, b1.y);
            ffma2(acc[3][0], a1.y, b0.x); ffma2(acc[3][1], a1.y, b0.y);
            ffma2(acc[3][2], a1.y, b1.x); ffma2(acc[3][3], a1.y, b1.y);
        }
        if (c + 1 < DD / KC3) {
            Xs[nxt][kk0 + 0][r0] = make_float2(xg[0].x, xg[0].x);
            Xs[nxt][kk0 + 1][r0] = make_float2(xg[0].y, xg[0].y);
            Xs[nxt][kk0 + 2][r0] = make_float2(xg[0].z, xg[0].z);
            Xs[nxt][kk0 + 3][r0] = make_float2(xg[0].w, xg[0].w);
            Xs[nxt][kk1 + 0][r1] = make_float2(xg[1].x, xg[1].x);
            Xs[nxt][kk1 + 1][r1] = make_float2(xg[1].y, xg[1].y);
            Xs[nxt][kk1 + 2][r1] = make_float2(xg[1].z, xg[1].z);
            Xs[nxt][kk1 + 3][r1] = make_float2(xg[1].w, xg[1].w);
            *(float4*)&Bs[nxt][t >> 4][(t & 15) * 4] = bg;
        }
        __syncthreads();
    }

    // ---- epilogue: scores + per-chunk softmax partials ----
    const float inv = 0.03125f;   // 1/sqrt(1024)
    float sv[4][8];
    #pragma unroll
    for (int i = 0; i < 4; ++i) {
        const int n = n0 + ty * 4 + i;
        const float dbv = g_db[(b << 12) + n];
        sv[i][0] = fmaf(f2lo(acc[i][0]), inv, dbv); sv[i][1] = fmaf(f2hi(acc[i][0]), inv, dbv);
        sv[i][2] = fmaf(f2lo(acc[i][1]), inv, dbv); sv[i][3] = fmaf(f2hi(acc[i][1]), inv, dbv);
        sv[i][4] = fmaf(f2lo(acc[i][2]), inv, dbv); sv[i][5] = fmaf(f2hi(acc[i][2]), inv, dbv);
        sv[i][6] = fmaf(f2lo(acc[i][3]), inv, dbv); sv[i][7] = fmaf(f2hi(acc[i][3]), inv, dbv);
        float* sp = &g_S[((size_t)(b << 12) + n) * NQ + tx * 8];
        *(float4*)sp       = make_float4(sv[i][0], sv[i][1], sv[i][2], sv[i][3]);
        *(float4*)(sp + 4) = make_float4(sv[i][4], sv[i][5], sv[i][6], sv[i][7]);
    }
    // per-thread (m,z) over its 4 n rows, per q; then tree over 32 ty-groups
    float2* red = &Xs[0][0][0];           // reuse smem: 32*64 float2 = 16KB
    #pragma unroll
    for (int jj = 0; jj < 8; ++jj) {
        float m = fmaxf(fmaxf(sv[0][jj], sv[1][jj]), fmaxf(sv[2][jj], sv[3][jj]));
        float z = expf(sv[0][jj] - m) + expf(sv[1][jj] - m)
                + expf(sv[2][jj] - m) + expf(sv[3][jj] - m);
        red[ty * 64 + tx * 8 + jj] = make_float2(m, z);
    }
    __syncthreads();
    if (t < 64) {
        float m = NEG_INF;
        #pragma unroll 8
        for (int g = 0; g < 32; ++g) m = fmaxf(m, red[g * 64 + t].x);
        float z = 0.f;
        #pragma unroll 8
        for (int g = 0; g < 32; ++g) {
            float2 v = red[g * 64 + t];
            z += v.y * expf(v.x - m);
        }
        g_pm[(b * 32 + blockIdx.x) * 64 + t] = m;
        g_pz[(b * 32 + blockIdx.x) * 64 + t] = z;
    }
}

// ---------------- K4b: combine partials -> lq = m + log z ----------------
__global__ void k4b_combine() {
    const int t = threadIdx.x;          // 512 = 8*64
    const int b = t >> 6, q = t & 63;
    float m = NEG_INF;
    for (int c = 0; c < 32; ++c) m = fmaxf(m, g_pm[(b * 32 + c) * 64 + q]);
    float z = 0.f;
    for (int c = 0; c < 32; ++c) z += g_pz[(b * 32 + c) * 64 + q] * expf(g_pm[(b * 32 + c) * 64 + q] - m);
    g_lq[b * 64 + q] = m + logf(z);
}

// ---------------- K5: r[b][n] = max_q (S - lq) ----------------
__global__ void k5_importance() {
    __shared__ float lqs[64];
    const int t = threadIdx.x;
    const int b = blockIdx.x >> 4;
    if (t < 64) lqs[t] = g_lq[b * 64 + t];
    __syncthreads();
    const int tok = blockIdx.x * 256 + t;
    const float4* row = (const float4*)&g_S[(size_t)tok * NQ];
    float m = NEG_INF;
    #pragma unroll
    for (int i = 0; i < 16; ++i) {
        float4 v = row[i];
        m = fmaxf(m, v.x - lqs[i * 4 + 0]);
        m = fmaxf(m, v.y - lqs[i * 4 + 1]);
        m = fmaxf(m, v.z - lqs[i * 4 + 2]);
        m = fmaxf(m, v.w - lqs[i * 4 + 3]);
    }
    g_r[tok] = m;
}

// ---------------- K6: radix top-k select (warp-parallel scans) ----------------
__device__ __forceinline__ unsigned ordkey(float f) {
    unsigned u = __float_as_uint(f);
    return (u & 0x80000000u) ? ~u : (u | 0x80000000u);
}
__global__ void k6_select() {
    __shared__ unsigned skey[4096];
    __shared__ unsigned hist[256];
    __shared__ unsigned wpart[8];
    __shared__ unsigned sh_selbin, sh_cum;
    const int t = threadIdx.x;          // 256 threads, 16 keys each
    const int lane = t & 31, w = t >> 5;
    const int b = blockIdx.x;

    #pragma unroll
    for (int i = 0; i < 4; ++i) {
        float4 v = *(const float4*)&g_r[(b << 12) + t * 16 + i * 4];
        skey[t * 16 + i * 4 + 0] = ordkey(v.x);
        skey[t * 16 + i * 4 + 1] = ordkey(v.y);
        skey[t * 16 + i * 4 + 2] = ordkey(v.z);
        skey[t * 16 + i * 4 + 3] = ordkey(v.w);
    }
    __syncthreads();

    unsigned prefix = 0, prefmask = 0, want = KTOP;
    #pragma unroll
    for (int shift = 24; shift >= 0; shift -= 8) {
        hist[t] = 0;
        __syncthreads();
        for (int e = 0; e < 16; ++e) {
            unsigned k = skey[t * 16 + e];
            if ((k & prefmask) == prefix) atomicAdd(&hist[(k >> shift) & 255u], 1u);
        }
        __syncthreads();
        // inclusive suffix sum over 256 bins (bin = t)
        unsigned h = hist[t];
        unsigned v = h;
        #pragma unroll
        for (int off = 1; off < 32; off <<= 1) {
            unsigned o = __shfl_down_sync(0xffffffffu, v, off);
            if (lane + off < 32) v += o;
        }
        if (lane == 0) wpart[w] = v;
        __syncthreads();
        unsigned above = 0;
        #pragma unroll
        for (int w2 = 0; w2 < 8; ++w2) if (w2 > w) above += wpart[w2];
        unsigned S = v + above;                    // sum of hist[t..255]
        if (S >= want && S - h < want) { sh_selbin = (unsigned)t; sh_cum = S - h; }
        __syncthreads();
        prefix  |= sh_selbin << shift;
        prefmask |= 0xFFu << shift;
        want    -= sh_cum;
        __syncthreads();
    }
    const unsigned T = prefix;
    const unsigned budget = want;

    unsigned cgt = 0, ceq = 0;
    for (int e = 0; e < 16; ++e) {
        unsigned k = skey[t * 16 + e];
        cgt += (k > T); ceq += (k == T);
    }
    // exclusive prefix scan of packed (cgt<<16 | ceq)
    unsigned pv = (cgt << 16) | ceq;
    unsigned iv = pv;
    #pragma unroll
    for (int off = 1; off < 32; off <<= 1) {
        unsigned o = __shfl_up_sync(0xffffffffu, iv, off);
        if (lane >= off) iv += o;
    }
    if (lane == 31) wpart[w] = iv;
    __syncthreads();
    unsigned below = 0;
    #pragma unroll
    for (int w2 = 0; w2 < 8; ++w2) if (w2 < w) below += wpart[w2];
    unsigned ex = iv - pv + below;
    unsigned gtb = ex >> 16, eqb = ex & 0xFFFFu;
    for (int e = 0; e < 16; ++e) {
        const int n = t * 16 + e;
        unsigned k = skey[n];
        if (k > T) {
            g_idx[b * KTOP + gtb + min(eqb, budget)] = n;
            gtb++;
        } else if (k == T) {
            if (eqb < budget) g_idx[b * KTOP + gtb + eqb] = n;
            eqb++;
        }
    }
}

// ---------------- K7: gather selected rows ----------------
__global__ void k7_gather(const float* __restrict__ X, float* __restrict__ out) {
    const int row = blockIdx.x;
    const int b = row >> 10;
    const int src = g_idx[row];
    const float4* s = (const float4*)&X[((size_t)(b << 12) + src) * (size_t)DD];
    float4* d = (float4*)&out[(size_t)row * DD];
    d[threadIdx.x] = s[threadIdx.x];
}

// ---------------- launch ----------------
extern "C" void kernel_launch(void* const* d_in, const int* in_sizes, int n_in,
                              void* d_out, int out_size) {
    const float* X    = (const float*)d_in[0];   // [8,4096,1024]
    const float* dens = (const float*)d_in[1];   // [8,4096]
    const float* qe   = (const float*)d_in[2];   // [64,1024]
    const float* kw   = (const float*)d_in[3];   // [1024,1024]
    // d_in[4] = key_b : per-query constant after Q·b -> softmax-invariant, dropped
    const float* w1   = (const float*)d_in[5];   // [1,2048]
    const float* b1   = (const float*)d_in[6];   // [2048]
    const float* w2   = (const float*)d_in[7];   // [2048,1]
    const float* b2   = (const float*)d_in[8];   // [1]
    float* out = (float*)d_out;

    k1_qw       <<<128, 256>>>(qe, kw);
    k2_density  <<<128, 256>>>(dens, w1, b1, w2, b2);
    k3_scores   <<<dim3(32, 8), 256>>>(X);
    k4b_combine <<<1, 512>>>();
    k5_importance<<<128, 256>>>();
    k6_select   <<<8, 256>>>();
    k7_gather   <<<8192, 256>>>(X, out);
}

// round 6
// speedup vs baseline: 1.5754x; 1.3712x over previous
#include <cuda_runtime.h>
#include <cstdint>

#define BB   8
#define NN   4096
#define DD   1024
#define NQ   64
#define KTOP 1024
#define NEG_INF (__int_as_float(0xff800000))

// ---------------- scratch ----------------
__device__ float g_QWT[DD * NQ];                    // QW transposed: [d][q]
__device__ float g_db [BB * NN];
__device__ float g_S  [(size_t)BB * NN * NQ];       // scores [b][n][q]
__device__ float g_pm [BB * 16 * NQ];               // partial max  [b][chunk256][q]
__device__ float g_pz [BB * 16 * NQ];
__device__ float g_r  [BB * NN];
__device__ int   g_idx[BB * KTOP];

// packed fp32x2 FMA: d = a*b + d on both halves
__device__ __forceinline__ void ffma2(unsigned long long& d,
                                      unsigned long long a,
                                      unsigned long long b) {
    asm("fma.rn.f32x2 %0, %1, %2, %0;" : "+l"(d) : "l"(a), "l"(b));
}
__device__ __forceinline__ unsigned long long dupf(float a) {
    unsigned long long d;
    asm("mov.b64 %0, {%1, %1};" : "=l"(d) : "f"(a));
    return d;
}
__device__ __forceinline__ float f2lo(unsigned long long v) { return __uint_as_float((unsigned)v); }
__device__ __forceinline__ float f2hi(unsigned long long v) { return __uint_as_float((unsigned)(v >> 32)); }

// ---------------- K12: fused k1 (QWT) + k2 (density bias) ----------------
// blocks 0..127: QWT[d][q] = sum_h qe[q][h]*kw[d][h]   (8 d-rows per block)
// blocks 128..255: density bias for 256 tokens each
__global__ void k12_pre(const float* __restrict__ qe, const float* __restrict__ kw,
                        const float* __restrict__ dens,
                        const float* __restrict__ w1, const float* __restrict__ b1,
                        const float* __restrict__ w2, const float* __restrict__ b2) {
    __shared__ __align__(16) char smraw[(64 * 132 + 8 * 132) * 4];
    const int t = threadIdx.x;

    if (blockIdx.x < 128) {
        float (*qs)[132] = (float(*)[132])smraw;
        float (*ks)[132] = (float(*)[132])(smraw + 64 * 132 * 4);
        const int j0 = blockIdx.x * 8;
        const int q  = t >> 2;
        const int jl = (t & 3) * 2;

        float acc0 = 0.f, acc1 = 0.f;
        for (int c = 0; c < 8; ++c) {
            const int k0 = c * 128;
            __syncthreads();
            #pragma unroll
            for (int p = 0; p < 8; ++p) {
                int f = t + 256 * p;
                int qq = f >> 5, kk = (f & 31) * 4;
                *(float4*)&qs[qq][kk] = *(const float4*)&qe[qq * 1024 + k0 + kk];
            }
            {
                int dr = t >> 5, kk = (t & 31) * 4;
                *(float4*)&ks[dr][kk] = *(const float4*)&kw[(j0 + dr) * 1024 + k0 + kk];
            }
            __syncthreads();
            #pragma unroll 8
            for (int kk = 0; kk < 128; kk += 4) {
                float4 a  = *(const float4*)&qs[q][kk];
                float4 b0 = *(const float4*)&ks[jl][kk];
                float4 b1 = *(const float4*)&ks[jl + 1][kk];
                acc0 += a.x * b0.x + a.y * b0.y + a.z * b0.z + a.w * b0.w;
                acc1 += a.x * b1.x + a.y * b1.y + a.z * b1.z + a.w * b1.w;
            }
        }
        g_QWT[(j0 + jl)     * 64 + q] = acc0;
        g_QWT[(j0 + jl + 1) * 64 + q] = acc1;
    } else {
        float4* w1s = (float4*)smraw;
        float4* b1s = w1s + 512;
        float4* w2s = b1s + 512;
        for (int i = t; i < 512; i += 256) {
            w1s[i] = ((const float4*)w1)[i];
            b1s[i] = ((const float4*)b1)[i];
            w2s[i] = ((const float4*)w2)[i];
        }
        __syncthreads();
        const int tok = (blockIdx.x - 128) * 256 + t;
        const float td = dens[tok];
        float s0 = 0.f, s1 = 0.f, s2 = 0.f, s3 = 0.f;
        #pragma unroll 4
        for (int j = 0; j < 512; ++j) {
            float4 a = w1s[j], bb = b1s[j], c = w2s[j];
            float h;
            h = fmaf(td, a.x, bb.x); s0 += fmaxf(h, 0.f) * c.x;
            h = fmaf(td, a.y, bb.y); s1 += fmaxf(h, 0.f) * c.y;
            h = fmaf(td, a.z, bb.z); s2 += fmaxf(h, 0.f) * c.z;
            h = fmaf(td, a.w, bb.w); s3 += fmaxf(h, 0.f) * c.w;
        }
        g_db[tok] = ((s0 + s1) + (s2 + s3)) + b2[0];
    }
}

// ---------------- K3: GEMM, 8x8 register tile, 1B smem / FMA ----------------
// grid (16, 8), 256 threads. CTA tile 256n x 64q, KC=16 double-buffered.
#define KC 16
__global__ void __launch_bounds__(256, 1)
k3_scores(const float* __restrict__ X) {
    __shared__ float  As[2][KC][256];     // [k][n], un-duplicated
    __shared__ float2 Bs[2][KC][32];      // [k][q-pair]
    const int b  = blockIdx.y;
    const int n0 = blockIdx.x * 256;
    const int t  = threadIdx.x;
    const int tx = t & 7, ty = t >> 3;    // tx: q-group (8q), ty: n-group (8n)
    const float* Xrow = X + ((size_t)b * NN + n0 + t) * (size_t)DD;
    const float* Brow = &g_QWT[(t >> 4) * 64 + (t & 15) * 4];

    unsigned long long acc[8][4];
    #pragma unroll
    for (int i = 0; i < 8; ++i)
        #pragma unroll
        for (int j = 0; j < 4; ++j) acc[i][j] = 0ull;

    // stage chunk 0
    {
        float4 xg[4];
        #pragma unroll
        for (int i = 0; i < 4; ++i) xg[i] = ((const float4*)Xrow)[i];
        float4 bg = *(const float4*)Brow;
        #pragma unroll
        for (int i = 0; i < 4; ++i) {
            As[0][i * 4 + 0][t] = xg[i].x;
            As[0][i * 4 + 1][t] = xg[i].y;
            As[0][i * 4 + 2][t] = xg[i].z;
            As[0][i * 4 + 3][t] = xg[i].w;
        }
        *(float4*)&Bs[0][t >> 4][(t & 15) * 2] = bg;
    }
    __syncthreads();

    #pragma unroll 1
    for (int c = 0; c < DD / KC; ++c) {
        const int buf = c & 1;
        float4 xg[4], bg;
        const bool more = (c + 1 < DD / KC);
        if (more) {
            const int k0 = (c + 1) * KC;
            #pragma unroll
            for (int i = 0; i < 4; ++i) xg[i] = *(const float4*)(Xrow + k0 + i * 4);
            bg = *(const float4*)(Brow + k0 * 64);
        }
        #pragma unroll
        for (int k = 0; k < KC; ++k) {
            float4 alo = *(const float4*)&As[buf][k][ty * 8];
            float4 ahi = *(const float4*)&As[buf][k][ty * 8 + 4];
            ulonglong2 bv0 = *(const ulonglong2*)&Bs[buf][k][tx * 4];
            ulonglong2 bv1 = *(const ulonglong2*)&Bs[buf][k][tx * 4 + 2];
            unsigned long long ad;
            ad = dupf(alo.x);
            ffma2(acc[0][0], ad, bv0.x); ffma2(acc[0][1], ad, bv0.y);
            ffma2(acc[0][2], ad, bv1.x); ffma2(acc[0][3], ad, bv1.y);
            ad = dupf(alo.y);
            ffma2(acc[1][0], ad, bv0.x); ffma2(acc[1][1], ad, bv0.y);
            ffma2(acc[1][2], ad, bv1.x); ffma2(acc[1][3], ad, bv1.y);
            ad = dupf(alo.z);
            ffma2(acc[2][0], ad, bv0.x); ffma2(acc[2][1], ad, bv0.y);
            ffma2(acc[2][2], ad, bv1.x); ffma2(acc[2][3], ad, bv1.y);
            ad = dupf(alo.w);
            ffma2(acc[3][0], ad, bv0.x); ffma2(acc[3][1], ad, bv0.y);
            ffma2(acc[3][2], ad, bv1.x); ffma2(acc[3][3], ad, bv1.y);
            ad = dupf(ahi.x);
            ffma2(acc[4][0], ad, bv0.x); ffma2(acc[4][1], ad, bv0.y);
            ffma2(acc[4][2], ad, bv1.x); ffma2(acc[4][3], ad, bv1.y);
            ad = dupf(ahi.y);
            ffma2(acc[5][0], ad, bv0.x); ffma2(acc[5][1], ad, bv0.y);
            ffma2(acc[5][2], ad, bv1.x); ffma2(acc[5][3], ad, bv1.y);
            ad = dupf(ahi.z);
            ffma2(acc[6][0], ad, bv0.x); ffma2(acc[6][1], ad, bv0.y);
            ffma2(acc[6][2], ad, bv1.x); ffma2(acc[6][3], ad, bv1.y);
            ad = dupf(ahi.w);
            ffma2(acc[7][0], ad, bv0.x); ffma2(acc[7][1], ad, bv0.y);
            ffma2(acc[7][2], ad, bv1.x); ffma2(acc[7][3], ad, bv1.y);
        }
        if (more) {
            const int nxt = buf ^ 1;
            #pragma unroll
            for (int i = 0; i < 4; ++i) {
                As[nxt][i * 4 + 0][t] = xg[i].x;
                As[nxt][i * 4 + 1][t] = xg[i].y;
                As[nxt][i * 4 + 2][t] = xg[i].z;
                As[nxt][i * 4 + 3][t] = xg[i].w;
            }
            *(float4*)&Bs[nxt][t >> 4][(t & 15) * 2] = bg;
        }
        __syncthreads();
    }

    // ---- epilogue: scores + per-256-chunk softmax partials ----
    const float inv = 0.03125f;   // 1/sqrt(1024)
    const int bq = tx * 8;
    float mq[8], zq[8];
    #pragma unroll
    for (int j = 0; j < 8; ++j) { mq[j] = NEG_INF; zq[j] = 0.f; }

    // pass 1: finalize + store + running max (recompute s in pass 2 to cap regs)
    #pragma unroll
    for (int i = 0; i < 8; ++i) {
        const int n = n0 + ty * 8 + i;
        const float dbv = g_db[(b << 12) + n];
        float s[8];
        #pragma unroll
        for (int j = 0; j < 4; ++j) {
            s[2 * j]     = fmaf(f2lo(acc[i][j]), inv, dbv);
            s[2 * j + 1] = fmaf(f2hi(acc[i][j]), inv, dbv);
        }
        float* sp = &g_S[((size_t)(b << 12) + n) * NQ + bq];
        *(float4*)sp       = make_float4(s[0], s[1], s[2], s[3]);
        *(float4*)(sp + 4) = make_float4(s[4], s[5], s[6], s[7]);
        #pragma unroll
        for (int j = 0; j < 8; ++j) mq[j] = fmaxf(mq[j], s[j]);
    }
    // pass 2: independent exps (throughput, not a serial chain)
    #pragma unroll
    for (int i = 0; i < 8; ++i) {
        const int n = n0 + ty * 8 + i;
        const float dbv = g_db[(b << 12) + n];
        #pragma unroll
        for (int j = 0; j < 4; ++j) {
            zq[2 * j]     += __expf(fmaf(f2lo(acc[i][j]), inv, dbv) - mq[2 * j]);
            zq[2 * j + 1] += __expf(fmaf(f2hi(acc[i][j]), inv, dbv) - mq[2 * j + 1]);
        }
    }

    float2* red = (float2*)&As[0][0][0];   // reuse: 32*64 float2 = 16KB
    #pragma unroll
    for (int j = 0; j < 8; ++j) red[ty * 64 + bq + j] = make_float2(mq[j], zq[j]);
    __syncthreads();
    if (t < 64) {
        float m = NEG_INF;
        #pragma unroll 8
        for (int g = 0; g < 32; ++g) m = fmaxf(m, red[g * 64 + t].x);
        float z = 0.f;
        #pragma unroll 8
        for (int g = 0; g < 32; ++g) { float2 v = red[g * 64 + t]; z += v.y * __expf(v.x - m); }
        g_pm[(b * 16 + blockIdx.x) * 64 + t] = m;
        g_pz[(b * 16 + blockIdx.x) * 64 + t] = z;
    }
}

// ---------------- K5: lq combine + r[b][n] = max_q (S - lq) ----------------
__global__ void k5_importance() {
    __shared__ float lqs[64];
    const int t = threadIdx.x;
    const int b = blockIdx.x >> 4;
    if (t < 64) {
        float m = NEG_INF;
        #pragma unroll
        for (int c = 0; c < 16; ++c) m = fmaxf(m, g_pm[(b * 16 + c) * 64 + t]);
        float z = 0.f;
        #pragma unroll
        for (int c = 0; c < 16; ++c) z += g_pz[(b * 16 + c) * 64 + t] * __expf(g_pm[(b * 16 + c) * 64 + t] - m);
        lqs[t] = m + logf(z);
    }
    __syncthreads();
    const int tok = blockIdx.x * 256 + t;
    const float4* row = (const float4*)&g_S[(size_t)tok * NQ];
    float m = NEG_INF;
    #pragma unroll
    for (int i = 0; i < 16; ++i) {
        float4 v = row[i];
        m = fmaxf(m, v.x - lqs[i * 4 + 0]);
        m = fmaxf(m, v.y - lqs[i * 4 + 1]);
        m = fmaxf(m, v.z - lqs[i * 4 + 2]);
        m = fmaxf(m, v.w - lqs[i * 4 + 3]);
    }
    g_r[tok] = m;
}

// ---------------- K6: radix top-k select (warp-parallel scans) ----------------
__device__ __forceinline__ unsigned ordkey(float f) {
    unsigned u = __float_as_uint(f);
    return (u & 0x80000000u) ? ~u : (u | 0x80000000u);
}
__global__ void k6_select() {
    __shared__ unsigned skey[4096];
    __shared__ unsigned hist[256];
    __shared__ unsigned wpart[8];
    __shared__ unsigned sh_selbin, sh_cum;
    const int t = threadIdx.x;
    const int lane = t & 31, w = t >> 5;
    const int b = blockIdx.x;

    #pragma unroll
    for (int i = 0; i < 4; ++i) {
        float4 v = *(const float4*)&g_r[(b << 12) + t * 16 + i * 4];
        skey[t * 16 + i * 4 + 0] = ordkey(v.x);
        skey[t * 16 + i * 4 + 1] = ordkey(v.y);
        skey[t * 16 + i * 4 + 2] = ordkey(v.z);
        skey[t * 16 + i * 4 + 3] = ordkey(v.w);
    }
    __syncthreads();

    unsigned prefix = 0, prefmask = 0, want = KTOP;
    #pragma unroll
    for (int shift = 24; shift >= 0; shift -= 8) {
        hist[t] = 0;
        __syncthreads();
        for (int e = 0; e < 16; ++e) {
            unsigned k = skey[t * 16 + e];
            if ((k & prefmask) == prefix) atomicAdd(&hist[(k >> shift) & 255u], 1u);
        }
        __syncthreads();
        unsigned h = hist[t];
        unsigned v = h;
        #pragma unroll
        for (int off = 1; off < 32; off <<= 1) {
            unsigned o = __shfl_down_sync(0xffffffffu, v, off);
            if (lane + off < 32) v += o;
        }
        if (lane == 0) wpart[w] = v;
        __syncthreads();
        unsigned above = 0;
        #pragma unroll
        for (int w2 = 0; w2 < 8; ++w2) if (w2 > w) above += wpart[w2];
        unsigned S = v + above;
        if (S >= want && S - h < want) { sh_selbin = (unsigned)t; sh_cum = S - h; }
        __syncthreads();
        prefix  |= sh_selbin << shift;
        prefmask |= 0xFFu << shift;
        want    -= sh_cum;
        __syncthreads();
    }
    const unsigned T = prefix;
    const unsigned budget = want;

    unsigned cgt = 0, ceq = 0;
    for (int e = 0; e < 16; ++e) {
        unsigned k = skey[t * 16 + e];
        cgt += (k > T); ceq += (k == T);
    }
    unsigned pv = (cgt << 16) | ceq;
    unsigned iv = pv;
    #pragma unroll
    for (int off = 1; off < 32; off <<= 1) {
        unsigned o = __shfl_up_sync(0xffffffffu, iv, off);
        if (lane >= off) iv += o;
    }
    if (lane == 31) wpart[w] = iv;
    __syncthreads();
    unsigned below = 0;
    #pragma unroll
    for (int w2 = 0; w2 < 8; ++w2) if (w2 < w) below += wpart[w2];
    unsigned ex = iv - pv + below;
    unsigned gtb = ex >> 16, eqb = ex & 0xFFFFu;
    for (int e = 0; e < 16; ++e) {
        const int n = t * 16 + e;
        unsigned k = skey[n];
        if (k > T) {
            g_idx[b * KTOP + gtb + min(eqb, budget)] = n;
            gtb++;
        } else if (k == T) {
            if (eqb < budget) g_idx[b * KTOP + gtb + eqb] = n;
            eqb++;
        }
    }
}

// ---------------- K7: gather selected rows ----------------
__global__ void k7_gather(const float* __restrict__ X, float* __restrict__ out) {
    const int row = blockIdx.x;
    const int b = row >> 10;
    const int src = g_idx[row];
    const float4* s = (const float4*)&X[((size_t)(b << 12) + src) * (size_t)DD];
    float4* d = (float4*)&out[(size_t)row * DD];
    d[threadIdx.x] = s[threadIdx.x];
}

// ---------------- launch ----------------
extern "C" void kernel_launch(void* const* d_in, const int* in_sizes, int n_in,
                              void* d_out, int out_size) {
    const float* X    = (const float*)d_in[0];
    const float* dens = (const float*)d_in[1];
    const float* qe   = (const float*)d_in[2];
    const float* kw   = (const float*)d_in[3];
    // d_in[4] = key_b: softmax-invariant per-query constant, dropped
    const float* w1   = (const float*)d_in[5];
    const float* b1   = (const float*)d_in[6];
    const float* w2   = (const float*)d_in[7];
    const float* b2   = (const float*)d_in[8];
    float* out = (float*)d_out;

    k12_pre      <<<256, 256>>>(qe, kw, dens, w1, b1, w2, b2);
    k3_scores    <<<dim3(16, 8), 256>>>(X);
    k5_importance<<<128, 256>>>();
    k6_select    <<<8, 256>>>();
    k7_gather    <<<8192, 256>>>(X, out);
}